// round 9
// baseline (speedup 1.0000x reference)
#include <cuda_runtime.h>
#include <cuda_fp16.h>
#include <mma.h>
#include <math.h>
#include <cstdint>

using namespace nvcuda;

#define Bdim 32
#define Tdim 32
#define Sdim 64
#define Hdim 1024
#define Edim 512
#define Vdim 32000
#define G3   3072
#define KX   1536
#define MROWS (Tdim*Bdim)
#define NBLK  (Vdim/64)
#define KSPL  4
#define BK    32
#define SLDA  40      // BK + 8 pad (halves)

// ---------------------------------------------------------------------------
__device__ __align__(16) __half d_wih0H[G3*KX];
__device__ __align__(16) __half d_wih0L[G3*KX];
__device__ __align__(16) __half d_whh0H[G3*Hdim];
__device__ __align__(16) __half d_whh0L[G3*Hdim];
__device__ __align__(16) __half d_wih1H[G3*Hdim];
__device__ __align__(16) __half d_wih1L[G3*Hdim];
__device__ __align__(16) __half d_whh1H[G3*Hdim];
__device__ __align__(16) __half d_whh1L[G3*Hdim];
__device__ __align__(16) __half d_WaH [Hdim*Hdim];
__device__ __align__(16) __half d_WaL [Hdim*Hdim];
__device__ __align__(16) __half d_WoutH[Hdim*2*Hdim];
__device__ __align__(16) __half d_WoutL[Hdim*2*Hdim];
__device__ __align__(16) __half d_ctxH[Bdim*Sdim*Hdim];
__device__ __align__(16) __half d_ctxL[Bdim*Sdim*Hdim];
__device__ __align__(16) __half d_Wgen[(size_t)Vdim*Hdim];
__device__ float  d_Ck [Bdim*Sdim*Hdim];
__device__ __align__(16) __half d_XH  [Tdim*Bdim*KX];
__device__ __align__(16) __half d_XL  [Tdim*Bdim*KX];
__device__ __align__(16) __half d_h0H [Bdim*Hdim];
__device__ __align__(16) __half d_h0L [Bdim*Hdim];
__device__ __align__(16) __half d_h1H [Bdim*Hdim];
__device__ __align__(16) __half d_h1L [Bdim*Hdim];
__device__ float  d_h0f[Bdim*Hdim];
__device__ float  d_h1f[Bdim*Hdim];
__device__ float  d_giP[KSPL*Bdim*G3];
__device__ float  d_ghP[KSPL*Bdim*G3];
__device__ float  d_oP [KSPL*Bdim*Hdim];
__device__ __align__(16) __half d_yH  [Bdim*2*Hdim];
__device__ __align__(16) __half d_yL  [Bdim*2*Hdim];
__device__ float  d_outf[Bdim*Hdim];
__device__ __align__(16) __half d_OutAll[MROWS*Hdim];
__device__ float  d_partM[MROWS*NBLK];
__device__ float  d_partS[MROWS*NBLK];
__device__ float  d_lse  [MROWS];

__device__ __forceinline__ void split_write(float v, __half* hi, __half* lo) {
    __half h = __float2half_rn(v);
    *hi = h;
    *lo = __float2half_rn(v - __half2float(h));
}

__device__ __forceinline__ void cp16(void* sdst, const void* gsrc) {
    unsigned int s = (unsigned int)__cvta_generic_to_shared(sdst);
    asm volatile("cp.async.cg.shared.global [%0], [%1], 16;\n" :: "r"(s), "l"(gsrc));
}
#define CP_COMMIT() asm volatile("cp.async.commit_group;\n" ::: "memory")
#define CP_WAIT(n)  asm volatile("cp.async.wait_group %0;\n" :: "n"(n) : "memory")

// ---------------------------------------------------------------------------
// Vectorized split convert: float4 in, 2x(4 halves as uint2) out.
// ---------------------------------------------------------------------------
__global__ void k_cvt4(const float4* __restrict__ src, __half* __restrict__ hi,
                       __half* __restrict__ lo, int n4) {
    int i = blockIdx.x*blockDim.x + threadIdx.x;
    if (i >= n4) return;
    float4 v = src[i];
    half2 h0 = __floats2half2_rn(v.x, v.y);
    half2 h1 = __floats2half2_rn(v.z, v.w);
    half2 l0 = __floats2half2_rn(v.x - __low2float(h0), v.y - __high2float(h0));
    half2 l1 = __floats2half2_rn(v.z - __low2float(h1), v.w - __high2float(h1));
    uint2 uh, ul;
    uh.x = *(unsigned*)&h0;  uh.y = *(unsigned*)&h1;
    ul.x = *(unsigned*)&l0;  ul.y = *(unsigned*)&l1;
    ((uint2*)hi)[i] = uh;
    ((uint2*)lo)[i] = ul;
}

// Plain fp16 convert, vectorized.
__global__ void k_f2h4(const float4* __restrict__ src, __half* __restrict__ dst, int n4) {
    int i = blockIdx.x*blockDim.x + threadIdx.x;
    if (i >= n4) return;
    float4 v = src[i];
    half2 h0 = __floats2half2_rn(v.x, v.y);
    half2 h1 = __floats2half2_rn(v.z, v.w);
    uint2 u;
    u.x = *(unsigned*)&h0;  u.y = *(unsigned*)&h1;
    ((uint2*)dst)[i] = u;
}

__global__ void k_embed(const int* __restrict__ wids, const int* __restrict__ sids,
                        const float* __restrict__ wemb, const float* __restrict__ semb) {
    int t = blockIdx.x, b = blockIdx.y;
    int wid = wids[b*Tdim + t];
    int sid = sids[b*Tdim + t];
    size_t base = (size_t)(t*Bdim + b)*KX;
    const float* wr = wemb + (size_t)wid*Edim;
    const float* sr = semb + (size_t)sid*Edim;
    for (int e = threadIdx.x; e < Edim; e += blockDim.x)
        split_write(wr[e] + sr[e], d_XH + base + e, d_XL + base + e);
}

__global__ void k_init(const float* __restrict__ hidden, const float* __restrict__ pout) {
    int i = blockIdx.x*blockDim.x + threadIdx.x;
    if (i >= Bdim*Hdim) return;
    int b = i / Hdim, j = i % Hdim;
    float h0 = hidden[i];
    float h1 = hidden[Bdim*Hdim + i];
    d_h0f[i] = h0;  d_h1f[i] = h1;
    split_write(h0, d_h0H + i, d_h0L + i);
    split_write(h1, d_h1H + i, d_h1L + i);
    size_t xo = (size_t)b*KX + Edim + j;
    split_write(pout[i], d_XH + xo, d_XL + xo);
}

// ---------------------------------------------------------------------------
// Ck = context @ Wa^T, pipelined smem GEMM. BM=64, BN=64, BK=32.
// grid (16, 32), 128 threads.
// ---------------------------------------------------------------------------
__global__ void k_ck() {
    __shared__ __align__(16) __half AsH[2][64*SLDA], AsL[2][64*SLDA];
    __shared__ __align__(16) __half BsH[2][64*SLDA], BsL[2][64*SLDA];
    int tid = threadIdx.x, warp = tid >> 5;
    int n0 = blockIdx.x*64, m0 = blockIdx.y*64;
    const int K = Hdim;
    wmma::fragment<wmma::accumulator,16,16,16,float> c[4];
    #pragma unroll
    for (int i = 0; i < 4; i++) wmma::fill_fragment(c[i], 0.f);

    auto load = [&](int st, int k0) {
        #pragma unroll
        for (int rep = 0; rep < 2; rep++) {
            int ch = tid + rep*128;
            int r = ch >> 2, p = ch & 3;
            cp16(&AsH[st][r*SLDA + p*8], d_ctxH + (size_t)(m0+r)*K + k0 + p*8);
            cp16(&AsL[st][r*SLDA + p*8], d_ctxL + (size_t)(m0+r)*K + k0 + p*8);
            cp16(&BsH[st][r*SLDA + p*8], d_WaH  + (size_t)(n0+r)*K + k0 + p*8);
            cp16(&BsL[st][r*SLDA + p*8], d_WaL  + (size_t)(n0+r)*K + k0 + p*8);
        }
    };
    load(0, 0);
    CP_COMMIT();
    const int nIter = K/BK;
    for (int it = 0; it < nIter; ++it) {
        int cur = it & 1;
        if (it + 1 < nIter) { load(cur^1, (it+1)*BK); CP_COMMIT(); CP_WAIT(1); }
        else CP_WAIT(0);
        __syncthreads();
        #pragma unroll
        for (int ks = 0; ks < 2; ks++) {
            wmma::fragment<wmma::matrix_b,16,16,16,__half,wmma::col_major> bH, bL;
            wmma::load_matrix_sync(bH, &BsH[cur][(warp*16)*SLDA + ks*16], SLDA);
            wmma::load_matrix_sync(bL, &BsL[cur][(warp*16)*SLDA + ks*16], SLDA);
            #pragma unroll
            for (int m = 0; m < 4; m++) {
                wmma::fragment<wmma::matrix_a,16,16,16,__half,wmma::row_major> aH, aL;
                wmma::load_matrix_sync(aH, &AsH[cur][(m*16)*SLDA + ks*16], SLDA);
                wmma::load_matrix_sync(aL, &AsL[cur][(m*16)*SLDA + ks*16], SLDA);
                wmma::mma_sync(c[m], aH, bH, c[m]);
                wmma::mma_sync(c[m], aH, bL, c[m]);
                wmma::mma_sync(c[m], aL, bH, c[m]);
            }
        }
        __syncthreads();
    }
    #pragma unroll
    for (int m = 0; m < 4; m++)
        wmma::store_matrix_sync(d_Ck + (size_t)(m0 + m*16)*Hdim + n0 + warp*16,
                                c[m], Hdim, wmma::mem_row_major);
}

// ---------------------------------------------------------------------------
// Dual GRU GEMM, smem-staged + cp.async pipeline, split-K via gridDim.y.
// grid (48, KSPL, 2), 128 threads. M=32, BN=64, BK=32.
// ---------------------------------------------------------------------------
__global__ void k_gru_gemm(const __half* __restrict__ XaH, const __half* __restrict__ XaL, int Ka,
                           const __half* __restrict__ WaH_, const __half* __restrict__ WaL_,
                           float* __restrict__ Ya,
                           const __half* __restrict__ XbH, const __half* __restrict__ XbL, int Kb,
                           const __half* __restrict__ WbH_, const __half* __restrict__ WbL_,
                           float* __restrict__ Yb, int N) {
    const __half *XH, *XL, *WH, *WL; float* Y; int K;
    if (blockIdx.z == 0) { XH = XaH; XL = XaL; WH = WaH_; WL = WaL_; Y = Ya; K = Ka; }
    else                 { XH = XbH; XL = XbL; WH = WbH_; WL = WbL_; Y = Yb; K = Kb; }
    __shared__ __align__(16) __half AsH[2][32*SLDA], AsL[2][32*SLDA];
    __shared__ __align__(16) __half BsH[2][64*SLDA], BsL[2][64*SLDA];
    int tid = threadIdx.x, warp = tid >> 5;
    int n0 = blockIdx.x*64;
    int kchunk = K / gridDim.y;
    int kbase = blockIdx.y * kchunk;

    wmma::fragment<wmma::accumulator,16,16,16,float> c[2];
    wmma::fill_fragment(c[0], 0.f);
    wmma::fill_fragment(c[1], 0.f);

    auto load = [&](int st, int k0) {
        {
            int r = tid >> 2, p = tid & 3;
            cp16(&AsH[st][r*SLDA + p*8], XH + (size_t)r*K + k0 + p*8);
            cp16(&AsL[st][r*SLDA + p*8], XL + (size_t)r*K + k0 + p*8);
        }
        #pragma unroll
        for (int rep = 0; rep < 2; rep++) {
            int ch = tid + rep*128;
            int r = ch >> 2, p = ch & 3;
            cp16(&BsH[st][r*SLDA + p*8], WH + (size_t)(n0+r)*K + k0 + p*8);
            cp16(&BsL[st][r*SLDA + p*8], WL + (size_t)(n0+r)*K + k0 + p*8);
        }
    };
    load(0, kbase);
    CP_COMMIT();
    const int nIter = kchunk/BK;
    for (int it = 0; it < nIter; ++it) {
        int cur = it & 1;
        if (it + 1 < nIter) { load(cur^1, kbase + (it+1)*BK); CP_COMMIT(); CP_WAIT(1); }
        else CP_WAIT(0);
        __syncthreads();
        #pragma unroll
        for (int ks = 0; ks < 2; ks++) {
            wmma::fragment<wmma::matrix_b,16,16,16,__half,wmma::col_major> bH, bL;
            wmma::load_matrix_sync(bH, &BsH[cur][(warp*16)*SLDA + ks*16], SLDA);
            wmma::load_matrix_sync(bL, &BsL[cur][(warp*16)*SLDA + ks*16], SLDA);
            #pragma unroll
            for (int m = 0; m < 2; m++) {
                wmma::fragment<wmma::matrix_a,16,16,16,__half,wmma::row_major> aH, aL;
                wmma::load_matrix_sync(aH, &AsH[cur][(m*16)*SLDA + ks*16], SLDA);
                wmma::load_matrix_sync(aL, &AsL[cur][(m*16)*SLDA + ks*16], SLDA);
                wmma::mma_sync(c[m], aH, bH, c[m]);
                wmma::mma_sync(c[m], aH, bL, c[m]);
                wmma::mma_sync(c[m], aL, bH, c[m]);
            }
        }
        __syncthreads();
    }
    float* Yp = Y + (size_t)blockIdx.y * Bdim * N;
    #pragma unroll
    for (int m = 0; m < 2; m++)
        wmma::store_matrix_sync(Yp + (size_t)(m*16)*N + n0 + warp*16, c[m],
                                N, wmma::mem_row_major);
}

// ---------------------------------------------------------------------------
__global__ void k_gate(const float* __restrict__ giP, const float* __restrict__ ghP,
                       const float* __restrict__ bih, const float* __restrict__ bhh,
                       float* __restrict__ hf, __half* __restrict__ hH, __half* __restrict__ hL,
                       int writeY) {
    int i = blockIdx.x*blockDim.x + threadIdx.x;
    if (i >= Bdim*Hdim) return;
    int b = i / Hdim, j = i % Hdim;
    size_t o0 = (size_t)b*G3 + j;
    const size_t PS = (size_t)Bdim*G3;
    float gr = 0.f, gz = 0.f, gn = 0.f, hr = 0.f, hz = 0.f, hn = 0.f;
    #pragma unroll
    for (int s = 0; s < KSPL; s++) {
        gr += giP[s*PS + o0];
        gz += giP[s*PS + o0 + Hdim];
        gn += giP[s*PS + o0 + 2*Hdim];
        hr += ghP[s*PS + o0];
        hz += ghP[s*PS + o0 + Hdim];
        hn += ghP[s*PS + o0 + 2*Hdim];
    }
    float r = 1.f/(1.f + expf(-(gr + bih[j]        + hr + bhh[j])));
    float z = 1.f/(1.f + expf(-(gz + bih[Hdim+j]   + hz + bhh[Hdim+j])));
    float n = tanhf(gn + bih[2*Hdim+j] + r*(hn + bhh[2*Hdim+j]));
    float h = (1.f - z)*n + z*hf[i];
    hf[i] = h;
    split_write(h, hH + i, hL + i);
    if (writeY) {
        size_t yo = (size_t)b*2*Hdim + Hdim + j;
        split_write(h, d_yH + yo, d_yL + yo);
    }
}

// ---------------------------------------------------------------------------
__global__ void k_attn(const float* __restrict__ context) {
    int b = blockIdx.x;
    int tid = threadIdx.x;
    __shared__ float qs[Hdim];
    __shared__ float sc[Sdim];
    for (int j = tid; j < Hdim; j += 256) qs[j] = d_h1f[(size_t)b*Hdim + j];
    __syncthreads();
    int warp = tid >> 5, lane = tid & 31;
    for (int s = warp; s < Sdim; s += 8) {
        const float* cr = d_Ck + (size_t)(b*Sdim + s)*Hdim;
        float sum = 0.f;
        for (int j = lane; j < Hdim; j += 32) sum += qs[j]*cr[j];
        #pragma unroll
        for (int o = 16; o; o >>= 1) sum += __shfl_xor_sync(0xffffffffu, sum, o);
        if (!lane) sc[s] = sum;
    }
    __syncthreads();
    float m = -1e30f;
    for (int s = 0; s < Sdim; s++) m = fmaxf(m, sc[s]);
    float ssum = 0.f;
    for (int s = 0; s < Sdim; s++) ssum += expf(sc[s] - m);
    __syncthreads();
    if (tid < Sdim) sc[tid] = expf(sc[tid] - m) / ssum;
    __syncthreads();
    const float* cb = context + (size_t)b*Sdim*Hdim;
    for (int j = tid; j < Hdim; j += 256) {
        float acc = 0.f;
        #pragma unroll 8
        for (int s = 0; s < Sdim; s++) acc += sc[s]*cb[(size_t)s*Hdim + j];
        size_t yo = (size_t)b*2*Hdim + j;
        split_write(acc, d_yH + yo, d_yL + yo);
    }
}

// ---------------------------------------------------------------------------
__global__ void k_out() {
    __shared__ __align__(16) __half AsH[2][32*SLDA], AsL[2][32*SLDA];
    __shared__ __align__(16) __half BsH[2][64*SLDA], BsL[2][64*SLDA];
    int tid = threadIdx.x, warp = tid >> 5;
    int n0 = blockIdx.x*64;
    const int K = 2*Hdim;
    int kchunk = K / gridDim.y;
    int kbase = blockIdx.y * kchunk;

    wmma::fragment<wmma::accumulator,16,16,16,float> c[2];
    wmma::fill_fragment(c[0], 0.f);
    wmma::fill_fragment(c[1], 0.f);

    auto load = [&](int st, int k0) {
        {
            int r = tid >> 2, p = tid & 3;
            cp16(&AsH[st][r*SLDA + p*8], d_yH + (size_t)r*K + k0 + p*8);
            cp16(&AsL[st][r*SLDA + p*8], d_yL + (size_t)r*K + k0 + p*8);
        }
        #pragma unroll
        for (int rep = 0; rep < 2; rep++) {
            int ch = tid + rep*128;
            int r = ch >> 2, p = ch & 3;
            cp16(&BsH[st][r*SLDA + p*8], d_WoutH + (size_t)(n0+r)*K + k0 + p*8);
            cp16(&BsL[st][r*SLDA + p*8], d_WoutL + (size_t)(n0+r)*K + k0 + p*8);
        }
    };
    load(0, kbase);
    CP_COMMIT();
    const int nIter = kchunk/BK;
    for (int it = 0; it < nIter; ++it) {
        int cur = it & 1;
        if (it + 1 < nIter) { load(cur^1, kbase + (it+1)*BK); CP_COMMIT(); CP_WAIT(1); }
        else CP_WAIT(0);
        __syncthreads();
        #pragma unroll
        for (int ks = 0; ks < 2; ks++) {
            wmma::fragment<wmma::matrix_b,16,16,16,__half,wmma::col_major> bH, bL;
            wmma::load_matrix_sync(bH, &BsH[cur][(warp*16)*SLDA + ks*16], SLDA);
            wmma::load_matrix_sync(bL, &BsL[cur][(warp*16)*SLDA + ks*16], SLDA);
            #pragma unroll
            for (int m = 0; m < 2; m++) {
                wmma::fragment<wmma::matrix_a,16,16,16,__half,wmma::row_major> aH, aL;
                wmma::load_matrix_sync(aH, &AsH[cur][(m*16)*SLDA + ks*16], SLDA);
                wmma::load_matrix_sync(aL, &AsL[cur][(m*16)*SLDA + ks*16], SLDA);
                wmma::mma_sync(c[m], aH, bH, c[m]);
                wmma::mma_sync(c[m], aH, bL, c[m]);
                wmma::mma_sync(c[m], aL, bH, c[m]);
            }
        }
        __syncthreads();
    }
    float* Yp = d_oP + (size_t)blockIdx.y * Bdim * Hdim;
    #pragma unroll
    for (int m = 0; m < 2; m++)
        wmma::store_matrix_sync(Yp + (size_t)(m*16)*Hdim + n0 + warp*16, c[m],
                                Hdim, wmma::mem_row_major);
}

// ---------------------------------------------------------------------------
__global__ void k_outfin(int t) {
    int i = blockIdx.x*blockDim.x + threadIdx.x;
    if (i >= Bdim*Hdim) return;
    int b = i / Hdim, j = i % Hdim;
    const size_t PS = (size_t)Bdim*Hdim;
    float acc = 0.f;
    #pragma unroll
    for (int s = 0; s < KSPL; s++) acc += d_oP[s*PS + i];
    float v = tanhf(acc);
    d_outf[i] = v;
    d_OutAll[(size_t)t*Bdim*Hdim + i] = __float2half_rn(v);
    if (t + 1 < Tdim) {
        size_t xo = (size_t)((t+1)*Bdim + b)*KX + Edim + j;
        split_write(v, d_XH + xo, d_XL + xo);
    }
}

// ---------------------------------------------------------------------------
// Generator GEMM. grid (500, 8), 256 threads.
// ---------------------------------------------------------------------------
#define GLDA 40
__global__ void k_gen(const float* __restrict__ bgen, float* __restrict__ logits) {
    __shared__ __align__(16) __half As[2][128*GLDA];
    __shared__ __align__(16) __half Bs[2][64*GLDA];
    __shared__ float Cs[64*68];
    int nb = blockIdx.x, mb = blockIdx.y;
    int n0 = nb*64, m0 = mb*128;
    int tid = threadIdx.x, warp = tid >> 5;
    int wm = warp >> 1, wn = warp & 1;
    const int K = Hdim;
    wmma::fragment<wmma::accumulator, 16,16,16, float> c[2][2];
    #pragma unroll
    for (int i = 0; i < 2; i++)
        #pragma unroll
        for (int j = 0; j < 2; j++)
            wmma::fill_fragment(c[i][j], 0.f);

    auto loadStage = [&](int stage, int kt) {
        int k0 = kt*32;
        #pragma unroll
        for (int rep = 0; rep < 2; rep++) {
            int ch = tid + rep*256;
            int row = ch >> 2, part = ch & 3;
            cp16(&As[stage][row*GLDA + part*8],
                 &d_OutAll[(size_t)(m0+row)*K + k0 + part*8]);
        }
        {
            int row = tid >> 2, part = tid & 3;
            cp16(&Bs[stage][row*GLDA + part*8],
                 &d_Wgen[(size_t)(n0+row)*K + k0 + part*8]);
        }
    };

    loadStage(0, 0);
    CP_COMMIT();
    const int nIter = K/32;
    for (int kt = 0; kt < nIter; ++kt) {
        int cur = kt & 1;
        if (kt + 1 < nIter) { loadStage(cur ^ 1, kt + 1); CP_COMMIT(); CP_WAIT(1); }
        else CP_WAIT(0);
        __syncthreads();
        #pragma unroll
        for (int s = 0; s < 32; s += 16) {
            wmma::fragment<wmma::matrix_a, 16,16,16, __half, wmma::row_major> a[2];
            wmma::fragment<wmma::matrix_b, 16,16,16, __half, wmma::col_major> bfr[2];
            #pragma unroll
            for (int i = 0; i < 2; i++)
                wmma::load_matrix_sync(a[i], &As[cur][(wm*32 + i*16)*GLDA + s], GLDA);
            #pragma unroll
            for (int j = 0; j < 2; j++)
                wmma::load_matrix_sync(bfr[j], &Bs[cur][(wn*32 + j*16)*GLDA + s], GLDA);
            #pragma unroll
            for (int i = 0; i < 2; i++)
                #pragma unroll
                for (int j = 0; j < 2; j++)
                    wmma::mma_sync(c[i][j], a[i], bfr[j], c[i][j]);
        }
        __syncthreads();
    }

    for (int hid = 0; hid < 2; ++hid) {
        if ((wm >> 1) == hid) {
            int wmL = wm & 1;
            #pragma unroll
            for (int i = 0; i < 2; i++)
                #pragma unroll
                for (int j = 0; j < 2; j++)
                    wmma::store_matrix_sync(&Cs[(wmL*32 + i*16)*68 + wn*32 + j*16],
                                            c[i][j], 68, wmma::mem_row_major);
        }
        __syncthreads();
        if (tid < 64) {
            int r = m0 + hid*64 + tid;
            float mx = -1e30f;
            for (int cc = 0; cc < 64; ++cc)
                mx = fmaxf(mx, Cs[tid*68 + cc] + bgen[n0 + cc]);
            float sm = 0.f;
            for (int cc = 0; cc < 64; ++cc)
                sm += expf(Cs[tid*68 + cc] + bgen[n0 + cc] - mx);
            d_partM[(size_t)r*NBLK + nb] = mx;
            d_partS[(size_t)r*NBLK + nb] = sm;
        }
        for (int e = tid; e < 64*64; e += 256) {
            int i = e >> 6, cc = e & 63;
            int r = m0 + hid*64 + i;
            logits[(size_t)r*Vdim + n0 + cc] = Cs[i*68 + cc] + bgen[n0 + cc];
        }
        __syncthreads();
    }
}

// ---------------------------------------------------------------------------
__global__ void k_combine() {
    int r = blockIdx.x, tid = threadIdx.x;
    float m = -1e30f, s = 0.f;
    for (int i = tid; i < NBLK; i += blockDim.x) {
        float mi = d_partM[(size_t)r*NBLK + i];
        float si = d_partS[(size_t)r*NBLK + i];
        float M = fmaxf(m, mi);
        s = s*expf(m - M) + si*expf(mi - M);
        m = M;
    }
    __shared__ float sm[128], ss[128];
    sm[tid] = m; ss[tid] = s;
    __syncthreads();
    for (int o = 64; o; o >>= 1) {
        if (tid < o) {
            float M = fmaxf(sm[tid], sm[tid+o]);
            ss[tid] = ss[tid]*expf(sm[tid] - M) + ss[tid+o]*expf(sm[tid+o] - M);
            sm[tid] = M;
        }
        __syncthreads();
    }
    if (!tid) d_lse[r] = sm[0] + logf(ss[0]);
}

__global__ void k_norm(float* __restrict__ logits) {
    int r = blockIdx.y;
    int i = blockIdx.x*blockDim.x + threadIdx.x;
    if (i < Vdim/4) {
        float4* p = (float4*)(logits + (size_t)r*Vdim);
        float l = d_lse[r];
        float4 v = p[i];
        v.x -= l; v.y -= l; v.z -= l; v.w -= l;
        p[i] = v;
    }
}

__global__ void k_final(float* __restrict__ tail) {
    int i = blockIdx.x*blockDim.x + threadIdx.x;
    const int BH = Bdim*Hdim;
    if (i < BH) {
        tail[i]        = d_h0f[i];
        tail[BH + i]   = d_h1f[i];
        tail[2*BH + i] = d_outf[i];
    }
}

// ---------------------------------------------------------------------------
extern "C" void kernel_launch(void* const* d_in, const int* in_sizes, int n_in,
                              void* d_out, int out_size) {
    (void)in_sizes; (void)n_in; (void)out_size;
    const int*   word_ids = (const int*)  d_in[0];
    const int*   spec_ids = (const int*)  d_in[1];
    const float* word_emb = (const float*)d_in[3];
    const float* spec_emb = (const float*)d_in[4];
    const float* wih0     = (const float*)d_in[5];
    const float* whh0     = (const float*)d_in[6];
    const float* bih0     = (const float*)d_in[7];
    const float* bhh0     = (const float*)d_in[8];
    const float* wih1     = (const float*)d_in[9];
    const float* whh1     = (const float*)d_in[10];
    const float* bih1     = (const float*)d_in[11];
    const float* bhh1     = (const float*)d_in[12];
    const float* Wa       = (const float*)d_in[13];
    const float* Wout     = (const float*)d_in[14];
    const float* Wgen     = (const float*)d_in[15];
    const float* bgen     = (const float*)d_in[16];
    const float* hidden   = (const float*)d_in[17];
    const float* pout     = (const float*)d_in[18];
    const float* context  = (const float*)d_in[19];
    float* outp = (float*)d_out;

    #define SYM(sym, ty, name) ty* name; { void* _p; cudaGetSymbolAddress(&_p, sym); name = (ty*)_p; }
    SYM(d_wih0H, __half, pwih0H)  SYM(d_wih0L, __half, pwih0L)
    SYM(d_whh0H, __half, pwhh0H)  SYM(d_whh0L, __half, pwhh0L)
    SYM(d_wih1H, __half, pwih1H)  SYM(d_wih1L, __half, pwih1L)
    SYM(d_whh1H, __half, pwhh1H)  SYM(d_whh1L, __half, pwhh1L)
    SYM(d_WaH,   __half, pWaH)    SYM(d_WaL,   __half, pWaL)
    SYM(d_WoutH, __half, pWoutH)  SYM(d_WoutL, __half, pWoutL)
    SYM(d_ctxH,  __half, pctxH)   SYM(d_ctxL,  __half, pctxL)
    SYM(d_Wgen,  __half, pWgen)
    SYM(d_XH,    __half, pXH)     SYM(d_XL,    __half, pXL)
    SYM(d_h0H,   __half, ph0H)    SYM(d_h0L,   __half, ph0L)
    SYM(d_h1H,   __half, ph1H)    SYM(d_h1L,   __half, ph1L)
    SYM(d_h0f,   float,  ph0f)    SYM(d_h1f,   float,  ph1f)
    SYM(d_giP,   float,  pgiP)    SYM(d_ghP,   float,  pghP)
    #undef SYM

    auto cvt4 = [&](const float* s, __half* hi, __half* lo, size_t n) {
        int n4 = (int)(n/4);
        k_cvt4<<<(n4 + 255)/256, 256>>>((const float4*)s, hi, lo, n4);
    };
    cvt4(wih0,    pwih0H, pwih0L, (size_t)G3*KX);
    cvt4(whh0,    pwhh0H, pwhh0L, (size_t)G3*Hdim);
    cvt4(wih1,    pwih1H, pwih1L, (size_t)G3*Hdim);
    cvt4(whh1,    pwhh1H, pwhh1L, (size_t)G3*Hdim);
    cvt4(Wa,      pWaH,   pWaL,   (size_t)Hdim*Hdim);
    cvt4(Wout,    pWoutH, pWoutL, (size_t)Hdim*2*Hdim);
    cvt4(context, pctxH,  pctxL,  (size_t)Bdim*Sdim*Hdim);
    {
        int n4 = (int)((size_t)Vdim*Hdim/4);
        k_f2h4<<<(n4 + 255)/256, 256>>>((const float4*)Wgen, pWgen, n4);
    }

    k_embed<<<dim3(Tdim, Bdim), 256>>>(word_ids, spec_ids, word_emb, spec_emb);
    k_init<<<(Bdim*Hdim + 255)/256, 256>>>(hidden, pout);
    k_ck<<<dim3(16, 32), 128>>>();

    const int BH = Bdim*Hdim;
    for (int t = 0; t < Tdim; ++t) {
        const __half* XtH = pXH + (size_t)t*Bdim*KX;
        const __half* XtL = pXL + (size_t)t*Bdim*KX;
        k_gru_gemm<<<dim3(48,KSPL,2), 128>>>(XtH, XtL, KX, pwih0H, pwih0L, pgiP,
                                             ph0H, ph0L, Hdim, pwhh0H, pwhh0L, pghP, G3);
        k_gate<<<(BH + 255)/256, 256>>>(pgiP, pghP, bih0, bhh0, ph0f, ph0H, ph0L, 0);
        k_gru_gemm<<<dim3(48,KSPL,2), 128>>>(ph0H, ph0L, Hdim, pwih1H, pwih1L, pgiP,
                                             ph1H, ph1L, Hdim, pwhh1H, pwhh1L, pghP, G3);
        k_gate<<<(BH + 255)/256, 256>>>(pgiP, pghP, bih1, bhh1, ph1f, ph1H, ph1L, 1);
        k_attn<<<Bdim, 256>>>(context);
        k_out<<<dim3(16,KSPL), 128>>>();
        k_outfin<<<(BH + 255)/256, 256>>>(t);
    }

    k_gen<<<dim3(NBLK, MROWS/128), 256>>>(bgen, outp);
    k_combine<<<MROWS, 128>>>();
    k_norm<<<dim3(32, MROWS), 256>>>(outp);
    k_final<<<(BH + 255)/256, 256>>>(outp + (size_t)MROWS*Vdim);
}

// round 10
// speedup vs baseline: 1.0364x; 1.0364x over previous
#include <cuda_runtime.h>
#include <cuda_fp16.h>
#include <mma.h>
#include <math.h>
#include <cstdint>

using namespace nvcuda;

#define Bdim 32
#define Tdim 32
#define Sdim 64
#define Hdim 1024
#define Edim 512
#define Vdim 32000
#define G3   3072
#define KX   1536
#define MROWS (Tdim*Bdim)
#define NBLK  (Vdim/64)
#define KSPL  4
#define BK    32
#define SLDA  40      // BK + 8 pad (halves)

// ---------------------------------------------------------------------------
__device__ __align__(16) __half d_wih0H[G3*KX];
__device__ __align__(16) __half d_wih0L[G3*KX];
__device__ __align__(16) __half d_whh0H[G3*Hdim];
__device__ __align__(16) __half d_whh0L[G3*Hdim];
__device__ __align__(16) __half d_wih1H[G3*Hdim];
__device__ __align__(16) __half d_wih1L[G3*Hdim];
__device__ __align__(16) __half d_whh1H[G3*Hdim];
__device__ __align__(16) __half d_whh1L[G3*Hdim];
__device__ __align__(16) __half d_WaH [Hdim*Hdim];
__device__ __align__(16) __half d_WaL [Hdim*Hdim];
__device__ __align__(16) __half d_WoutH[Hdim*2*Hdim];
__device__ __align__(16) __half d_WoutL[Hdim*2*Hdim];
__device__ __align__(16) __half d_ctxH[Bdim*Sdim*Hdim];
__device__ __align__(16) __half d_ctxL[Bdim*Sdim*Hdim];
__device__ __align__(16) __half d_Wgen[(size_t)Vdim*Hdim];
__device__ float  d_Ck [Bdim*Sdim*Hdim];
__device__ __align__(16) __half d_EH  [MROWS*Edim];      // embeddings, split
__device__ __align__(16) __half d_EL  [MROWS*Edim];
__device__ __align__(16) __half d_XfH [MROWS*Hdim];      // input-feed (out part)
__device__ __align__(16) __half d_XfL [MROWS*Hdim];
__device__ float  d_preGi[(size_t)MROWS*G3];             // emb @ wih0[:, :E]^T
__device__ __align__(16) __half d_h0H [Bdim*Hdim];
__device__ __align__(16) __half d_h0L [Bdim*Hdim];
__device__ __align__(16) __half d_h1H [Bdim*Hdim];
__device__ __align__(16) __half d_h1L [Bdim*Hdim];
__device__ float  d_h0f[Bdim*Hdim];
__device__ float  d_h1f[Bdim*Hdim];
__device__ float  d_giP[KSPL*Bdim*G3];
__device__ float  d_ghP[KSPL*Bdim*G3];
__device__ float  d_oP [KSPL*Bdim*Hdim];
__device__ __align__(16) __half d_yH  [Bdim*2*Hdim];
__device__ __align__(16) __half d_yL  [Bdim*2*Hdim];
__device__ float  d_outf[Bdim*Hdim];
__device__ __align__(16) __half d_OutAll[MROWS*Hdim];
__device__ float  d_partM[MROWS*NBLK];
__device__ float  d_partS[MROWS*NBLK];
__device__ float  d_lse  [MROWS];
__device__ int    d_ctr  [16];

__device__ __forceinline__ void split_write(float v, __half* hi, __half* lo) {
    __half h = __float2half_rn(v);
    *hi = h;
    *lo = __float2half_rn(v - __half2float(h));
}

__device__ __forceinline__ void cp16(void* sdst, const void* gsrc) {
    unsigned int s = (unsigned int)__cvta_generic_to_shared(sdst);
    asm volatile("cp.async.cg.shared.global [%0], [%1], 16;\n" :: "r"(s), "l"(gsrc));
}
#define CP_COMMIT() asm volatile("cp.async.commit_group;\n" ::: "memory")
#define CP_WAIT(n)  asm volatile("cp.async.wait_group %0;\n" :: "n"(n) : "memory")

// ---------------------------------------------------------------------------
// ONE vectorized convert kernel for everything.
// Region bounds in float4 units.
// ---------------------------------------------------------------------------
#define C1 1179648u              // wih0
#define C2 1966080u              // whh0
#define C3 2752512u              // wih1
#define C4 3538944u              // whh1
#define C5 3801088u              // Wa
#define C6 4325376u              // Wout
#define C7 4849664u              // ctx
#define CT 13041664u             // + Wgen

__device__ __forceinline__ void split4(float4 v, __half* hi, __half* lo, size_t i4) {
    half2 h0 = __floats2half2_rn(v.x, v.y);
    half2 h1 = __floats2half2_rn(v.z, v.w);
    half2 l0 = __floats2half2_rn(v.x - __low2float(h0), v.y - __high2float(h0));
    half2 l1 = __floats2half2_rn(v.z - __low2float(h1), v.w - __high2float(h1));
    uint2 uh, ul;
    uh.x = *(unsigned*)&h0;  uh.y = *(unsigned*)&h1;
    ul.x = *(unsigned*)&l0;  ul.y = *(unsigned*)&l1;
    ((uint2*)hi)[i4] = uh;
    ((uint2*)lo)[i4] = ul;
}

__global__ void k_cvt_all(const float4* __restrict__ wih0, const float4* __restrict__ whh0,
                          const float4* __restrict__ wih1, const float4* __restrict__ whh1,
                          const float4* __restrict__ Wa,   const float4* __restrict__ Wout,
                          const float4* __restrict__ ctx,  const float4* __restrict__ Wgen) {
    unsigned i = blockIdx.x*blockDim.x + threadIdx.x;
    if (i >= CT) return;
    if      (i < C1) { size_t j = i;      split4(wih0[j], d_wih0H, d_wih0L, j); }
    else if (i < C2) { size_t j = i - C1; split4(whh0[j], d_whh0H, d_whh0L, j); }
    else if (i < C3) { size_t j = i - C2; split4(wih1[j], d_wih1H, d_wih1L, j); }
    else if (i < C4) { size_t j = i - C3; split4(whh1[j], d_whh1H, d_whh1L, j); }
    else if (i < C5) { size_t j = i - C4; split4(Wa[j],   d_WaH,   d_WaL,   j); }
    else if (i < C6) { size_t j = i - C5; split4(Wout[j], d_WoutH, d_WoutL, j); }
    else if (i < C7) { size_t j = i - C6; split4(ctx[j],  d_ctxH,  d_ctxL,  j); }
    else {
        size_t j = i - C7;
        float4 v = Wgen[j];
        half2 h0 = __floats2half2_rn(v.x, v.y);
        half2 h1 = __floats2half2_rn(v.z, v.w);
        uint2 u; u.x = *(unsigned*)&h0; u.y = *(unsigned*)&h1;
        ((uint2*)d_Wgen)[j] = u;
    }
}

// ---------------------------------------------------------------------------
// Merged embed + init. Blocks [0,1024): embedding gather; [1024,1152): state init.
// ---------------------------------------------------------------------------
__global__ void k_embed_init(const int* __restrict__ wids, const int* __restrict__ sids,
                             const float* __restrict__ wemb, const float* __restrict__ semb,
                             const float* __restrict__ hidden, const float* __restrict__ pout) {
    int bid = blockIdx.x;
    if (bid < MROWS) {
        int t = bid >> 5, b = bid & 31;
        int wid = wids[b*Tdim + t];
        int sid = sids[b*Tdim + t];
        size_t base = (size_t)bid*Edim;
        const float* wr = wemb + (size_t)wid*Edim;
        const float* sr = semb + (size_t)sid*Edim;
        for (int e = threadIdx.x; e < Edim; e += blockDim.x)
            split_write(wr[e] + sr[e], d_EH + base + e, d_EL + base + e);
    } else {
        int i = (bid - MROWS)*256 + threadIdx.x;
        if (i >= Bdim*Hdim) return;
        float h0 = hidden[i];
        float h1 = hidden[Bdim*Hdim + i];
        d_h0f[i] = h0;  d_h1f[i] = h1;
        split_write(h0, d_h0H + i, d_h0L + i);
        split_write(h1, d_h1H + i, d_h1L + i);
        split_write(pout[i], d_XfH + i, d_XfL + i);
        if (i < 16) d_ctr[i] = 0;
    }
}

// ---------------------------------------------------------------------------
// 64x64 pipelined split-fp16 GEMM tile (C = A @ B^T).
// ---------------------------------------------------------------------------
__device__ __forceinline__ void gemm64(
    const __half* __restrict__ AH, const __half* __restrict__ AL, int As,
    const __half* __restrict__ BH, const __half* __restrict__ BL, int Bs,
    int K, float* __restrict__ C, int Cs, int m0, int n0, int tid,
    __half* sAH, __half* sAL, __half* sBH, __half* sBL)
{
    int warp = tid >> 5;
    const int STG = 64*SLDA;
    wmma::fragment<wmma::accumulator,16,16,16,float> c[4];
    #pragma unroll
    for (int i = 0; i < 4; i++) wmma::fill_fragment(c[i], 0.f);
    auto load = [&](int st, int k0) {
        #pragma unroll
        for (int rep = 0; rep < 2; rep++) {
            int ch = tid + rep*128;
            int r = ch >> 2, p = ch & 3;
            cp16(&sAH[st*STG + r*SLDA + p*8], AH + (size_t)(m0+r)*As + k0 + p*8);
            cp16(&sAL[st*STG + r*SLDA + p*8], AL + (size_t)(m0+r)*As + k0 + p*8);
            cp16(&sBH[st*STG + r*SLDA + p*8], BH + (size_t)(n0+r)*Bs + k0 + p*8);
            cp16(&sBL[st*STG + r*SLDA + p*8], BL + (size_t)(n0+r)*Bs + k0 + p*8);
        }
    };
    load(0, 0);
    CP_COMMIT();
    const int nIter = K/BK;
    for (int it = 0; it < nIter; ++it) {
        int cur = it & 1;
        if (it + 1 < nIter) { load(cur^1, (it+1)*BK); CP_COMMIT(); CP_WAIT(1); }
        else CP_WAIT(0);
        __syncthreads();
        #pragma unroll
        for (int ks = 0; ks < 2; ks++) {
            wmma::fragment<wmma::matrix_b,16,16,16,__half,wmma::col_major> bH, bL;
            wmma::load_matrix_sync(bH, &sBH[cur*STG + (warp*16)*SLDA + ks*16], SLDA);
            wmma::load_matrix_sync(bL, &sBL[cur*STG + (warp*16)*SLDA + ks*16], SLDA);
            #pragma unroll
            for (int m = 0; m < 4; m++) {
                wmma::fragment<wmma::matrix_a,16,16,16,__half,wmma::row_major> aH, aL;
                wmma::load_matrix_sync(aH, &sAH[cur*STG + (m*16)*SLDA + ks*16], SLDA);
                wmma::load_matrix_sync(aL, &sAL[cur*STG + (m*16)*SLDA + ks*16], SLDA);
                wmma::mma_sync(c[m], aH, bH, c[m]);
                wmma::mma_sync(c[m], aH, bL, c[m]);
                wmma::mma_sync(c[m], aL, bH, c[m]);
            }
        }
        __syncthreads();
    }
    #pragma unroll
    for (int m = 0; m < 4; m++)
        wmma::store_matrix_sync(C + (size_t)(m0 + m*16)*Cs + n0 + warp*16,
                                c[m], Cs, wmma::mem_row_major);
}

// ---------------------------------------------------------------------------
// Prep kernel: z=0 -> Ck = ctx @ Wa^T;  z=1 -> preGi = emb @ wih0[:, :E]^T.
// grid (48, 32, 2), 128 threads.
// ---------------------------------------------------------------------------
__global__ void k_prep() {
    __shared__ __align__(16) __half sAH[2*64*SLDA], sAL[2*64*SLDA];
    __shared__ __align__(16) __half sBH[2*64*SLDA], sBL[2*64*SLDA];
    int tid = threadIdx.x;
    if (blockIdx.z == 0) {
        if (blockIdx.x >= 16) return;
        gemm64(d_ctxH, d_ctxL, Hdim, d_WaH, d_WaL, Hdim, Hdim,
               d_Ck, Hdim, blockIdx.y*64, blockIdx.x*64, tid, sAH, sAL, sBH, sBL);
    } else {
        if (blockIdx.y >= 16) return;
        gemm64(d_EH, d_EL, Edim, d_wih0H, d_wih0L, KX, Edim,
               d_preGi, G3, blockIdx.y*64, blockIdx.x*64, tid, sAH, sAL, sBH, sBL);
    }
}

// ---------------------------------------------------------------------------
// Dual GRU GEMM, smem-staged pipeline, split-K. grid (48, KSPL, 2), 128 thr.
// W row stride passed separately (layer-0 gi uses wih0 with stride KX).
// ---------------------------------------------------------------------------
__global__ void k_gru_gemm(const __half* __restrict__ XaH, const __half* __restrict__ XaL, int Ka,
                           const __half* __restrict__ WaH_, const __half* __restrict__ WaL_, int Wsa,
                           float* __restrict__ Ya,
                           const __half* __restrict__ XbH, const __half* __restrict__ XbL, int Kb,
                           const __half* __restrict__ WbH_, const __half* __restrict__ WbL_, int Wsb,
                           float* __restrict__ Yb, int N) {
    const __half *XH, *XL, *WH, *WL; float* Y; int K, Ws;
    if (blockIdx.z == 0) { XH = XaH; XL = XaL; WH = WaH_; WL = WaL_; Y = Ya; K = Ka; Ws = Wsa; }
    else                 { XH = XbH; XL = XbL; WH = WbH_; WL = WbL_; Y = Yb; K = Kb; Ws = Wsb; }
    __shared__ __align__(16) __half AsH[2][32*SLDA], AsL[2][32*SLDA];
    __shared__ __align__(16) __half BsH[2][64*SLDA], BsL[2][64*SLDA];
    int tid = threadIdx.x, warp = tid >> 5;
    int n0 = blockIdx.x*64;
    int kchunk = K / gridDim.y;
    int kbase = blockIdx.y * kchunk;

    wmma::fragment<wmma::accumulator,16,16,16,float> c[2];
    wmma::fill_fragment(c[0], 0.f);
    wmma::fill_fragment(c[1], 0.f);

    auto load = [&](int st, int k0) {
        {
            int r = tid >> 2, p = tid & 3;
            cp16(&AsH[st][r*SLDA + p*8], XH + (size_t)r*K + k0 + p*8);
            cp16(&AsL[st][r*SLDA + p*8], XL + (size_t)r*K + k0 + p*8);
        }
        #pragma unroll
        for (int rep = 0; rep < 2; rep++) {
            int ch = tid + rep*128;
            int r = ch >> 2, p = ch & 3;
            cp16(&BsH[st][r*SLDA + p*8], WH + (size_t)(n0+r)*Ws + k0 + p*8);
            cp16(&BsL[st][r*SLDA + p*8], WL + (size_t)(n0+r)*Ws + k0 + p*8);
        }
    };
    load(0, kbase);
    CP_COMMIT();
    const int nIter = kchunk/BK;
    for (int it = 0; it < nIter; ++it) {
        int cur = it & 1;
        if (it + 1 < nIter) { load(cur^1, kbase + (it+1)*BK); CP_COMMIT(); CP_WAIT(1); }
        else CP_WAIT(0);
        __syncthreads();
        #pragma unroll
        for (int ks = 0; ks < 2; ks++) {
            wmma::fragment<wmma::matrix_b,16,16,16,__half,wmma::col_major> bH, bL;
            wmma::load_matrix_sync(bH, &BsH[cur][(warp*16)*SLDA + ks*16], SLDA);
            wmma::load_matrix_sync(bL, &BsL[cur][(warp*16)*SLDA + ks*16], SLDA);
            #pragma unroll
            for (int m = 0; m < 2; m++) {
                wmma::fragment<wmma::matrix_a,16,16,16,__half,wmma::row_major> aH, aL;
                wmma::load_matrix_sync(aH, &AsH[cur][(m*16)*SLDA + ks*16], SLDA);
                wmma::load_matrix_sync(aL, &AsL[cur][(m*16)*SLDA + ks*16], SLDA);
                wmma::mma_sync(c[m], aH, bH, c[m]);
                wmma::mma_sync(c[m], aH, bL, c[m]);
                wmma::mma_sync(c[m], aL, bH, c[m]);
            }
        }
        __syncthreads();
    }
    float* Yp = Y + (size_t)blockIdx.y * Bdim * N;
    #pragma unroll
    for (int m = 0; m < 2; m++)
        wmma::store_matrix_sync(Yp + (size_t)(m*16)*N + n0 + warp*16, c[m],
                                N, wmma::mem_row_major);
}

// ---------------------------------------------------------------------------
// GRU gate; sums KSPL partials (+ optional precomputed embedding term).
// ---------------------------------------------------------------------------
__global__ void k_gate(const float* __restrict__ giP, const float* __restrict__ ghP,
                       const float* __restrict__ gpre,
                       const float* __restrict__ bih, const float* __restrict__ bhh,
                       float* __restrict__ hf, __half* __restrict__ hH, __half* __restrict__ hL,
                       int writeY) {
    int i = blockIdx.x*blockDim.x + threadIdx.x;
    if (i >= Bdim*Hdim) return;
    int b = i / Hdim, j = i % Hdim;
    size_t o0 = (size_t)b*G3 + j;
    const size_t PS = (size_t)Bdim*G3;
    float gr = 0.f, gz = 0.f, gn = 0.f, hr = 0.f, hz = 0.f, hn = 0.f;
    #pragma unroll
    for (int s = 0; s < KSPL; s++) {
        gr += giP[s*PS + o0];
        gz += giP[s*PS + o0 + Hdim];
        gn += giP[s*PS + o0 + 2*Hdim];
        hr += ghP[s*PS + o0];
        hz += ghP[s*PS + o0 + Hdim];
        hn += ghP[s*PS + o0 + 2*Hdim];
    }
    if (gpre) {
        gr += gpre[o0];
        gz += gpre[o0 + Hdim];
        gn += gpre[o0 + 2*Hdim];
    }
    float r = 1.f/(1.f + expf(-(gr + bih[j]        + hr + bhh[j])));
    float z = 1.f/(1.f + expf(-(gz + bih[Hdim+j]   + hz + bhh[Hdim+j])));
    float n = tanhf(gn + bih[2*Hdim+j] + r*(hn + bhh[2*Hdim+j]));
    float h = (1.f - z)*n + z*hf[i];
    hf[i] = h;
    split_write(h, hH + i, hL + i);
    if (writeY) {
        size_t yo = (size_t)b*2*Hdim + Hdim + j;
        split_write(h, d_yH + yo, d_yL + yo);
    }
}

// ---------------------------------------------------------------------------
// Attention per batch row; scores = fp32 h1 · Ck. grid (32), 256 threads.
// ---------------------------------------------------------------------------
__global__ void k_attn(const float* __restrict__ context) {
    int b = blockIdx.x;
    int tid = threadIdx.x;
    __shared__ float qs[Hdim];
    __shared__ float sc[Sdim];
    for (int j = tid; j < Hdim; j += 256) qs[j] = d_h1f[(size_t)b*Hdim + j];
    __syncthreads();
    int warp = tid >> 5, lane = tid & 31;
    for (int s = warp; s < Sdim; s += 8) {
        const float* cr = d_Ck + (size_t)(b*Sdim + s)*Hdim;
        float sum = 0.f;
        for (int j = lane; j < Hdim; j += 32) sum += qs[j]*cr[j];
        #pragma unroll
        for (int o = 16; o; o >>= 1) sum += __shfl_xor_sync(0xffffffffu, sum, o);
        if (!lane) sc[s] = sum;
    }
    __syncthreads();
    float m = -1e30f;
    for (int s = 0; s < Sdim; s++) m = fmaxf(m, sc[s]);
    float ssum = 0.f;
    for (int s = 0; s < Sdim; s++) ssum += expf(sc[s] - m);
    __syncthreads();
    if (tid < Sdim) sc[tid] = expf(sc[tid] - m) / ssum;
    __syncthreads();
    const float* cb = context + (size_t)b*Sdim*Hdim;
    for (int j = tid; j < Hdim; j += 256) {
        float acc = 0.f;
        #pragma unroll 8
        for (int s = 0; s < Sdim; s++) acc += sc[s]*cb[(size_t)s*Hdim + j];
        size_t yo = (size_t)b*2*Hdim + j;
        split_write(acc, d_yH + yo, d_yL + yo);
    }
}

// ---------------------------------------------------------------------------
// out GEMM + fused finish (last split-K block per n-tile does tanh+scatter).
// grid (16, KSPL), 128 threads.
// ---------------------------------------------------------------------------
__global__ void k_out(int t) {
    __shared__ __align__(16) __half AsH[2][32*SLDA], AsL[2][32*SLDA];
    __shared__ __align__(16) __half BsH[2][64*SLDA], BsL[2][64*SLDA];
    int tid = threadIdx.x, warp = tid >> 5;
    int n0 = blockIdx.x*64;
    const int K = 2*Hdim;
    int kchunk = K / gridDim.y;
    int kbase = blockIdx.y * kchunk;

    wmma::fragment<wmma::accumulator,16,16,16,float> c[2];
    wmma::fill_fragment(c[0], 0.f);
    wmma::fill_fragment(c[1], 0.f);

    auto load = [&](int st, int k0) {
        {
            int r = tid >> 2, p = tid & 3;
            cp16(&AsH[st][r*SLDA + p*8], d_yH + (size_t)r*K + k0 + p*8);
            cp16(&AsL[st][r*SLDA + p*8], d_yL + (size_t)r*K + k0 + p*8);
        }
        #pragma unroll
        for (int rep = 0; rep < 2; rep++) {
            int ch = tid + rep*128;
            int r = ch >> 2, p = ch & 3;
            cp16(&BsH[st][r*SLDA + p*8], d_WoutH + (size_t)(n0+r)*K + k0 + p*8);
            cp16(&BsL[st][r*SLDA + p*8], d_WoutL + (size_t)(n0+r)*K + k0 + p*8);
        }
    };
    load(0, kbase);
    CP_COMMIT();
    const int nIter = kchunk/BK;
    for (int it = 0; it < nIter; ++it) {
        int cur = it & 1;
        if (it + 1 < nIter) { load(cur^1, kbase + (it+1)*BK); CP_COMMIT(); CP_WAIT(1); }
        else CP_WAIT(0);
        __syncthreads();
        #pragma unroll
        for (int ks = 0; ks < 2; ks++) {
            wmma::fragment<wmma::matrix_b,16,16,16,__half,wmma::col_major> bH, bL;
            wmma::load_matrix_sync(bH, &BsH[cur][(warp*16)*SLDA + ks*16], SLDA);
            wmma::load_matrix_sync(bL, &BsL[cur][(warp*16)*SLDA + ks*16], SLDA);
            #pragma unroll
            for (int m = 0; m < 2; m++) {
                wmma::fragment<wmma::matrix_a,16,16,16,__half,wmma::row_major> aH, aL;
                wmma::load_matrix_sync(aH, &AsH[cur][(m*16)*SLDA + ks*16], SLDA);
                wmma::load_matrix_sync(aL, &AsL[cur][(m*16)*SLDA + ks*16], SLDA);
                wmma::mma_sync(c[m], aH, bH, c[m]);
                wmma::mma_sync(c[m], aH, bL, c[m]);
                wmma::mma_sync(c[m], aL, bH, c[m]);
            }
        }
        __syncthreads();
    }
    float* Yp = d_oP + (size_t)blockIdx.y * Bdim * Hdim;
    #pragma unroll
    for (int m = 0; m < 2; m++)
        wmma::store_matrix_sync(Yp + (size_t)(m*16)*Hdim + n0 + warp*16, c[m],
                                Hdim, wmma::mem_row_major);

    // fused finish: last of the KSPL blocks for this n-tile sums + tanh + scatters
    __threadfence();
    __shared__ int isLast;
    if (tid == 0) {
        int v = atomicAdd(&d_ctr[blockIdx.x], 1);
        isLast = (v == (int)gridDim.y - 1);
    }
    __syncthreads();
    if (isLast) {
        __threadfence();   // acquire: see other blocks' partial stores
        const size_t PS = (size_t)Bdim*Hdim;
        for (int e = tid; e < Bdim*64; e += 128) {
            int row = e >> 6, cc = e & 63;
            size_t idx = (size_t)row*Hdim + n0 + cc;
            float acc = d_oP[idx] + d_oP[PS+idx] + d_oP[2*PS+idx] + d_oP[3*PS+idx];
            float v = tanhf(acc);
            d_outf[idx] = v;
            d_OutAll[(size_t)t*PS + idx] = __float2half_rn(v);
            if (t + 1 < Tdim)
                split_write(v, d_XfH + (size_t)(t+1)*PS + idx, d_XfL + (size_t)(t+1)*PS + idx);
        }
        __syncthreads();
        if (tid == 0) d_ctr[blockIdx.x] = 0;
    }
}

// ---------------------------------------------------------------------------
// Generator GEMM. grid (500, 8), 256 threads.
// ---------------------------------------------------------------------------
#define GLDA 40
__global__ void k_gen(const float* __restrict__ bgen, float* __restrict__ logits) {
    __shared__ __align__(16) __half As[2][128*GLDA];
    __shared__ __align__(16) __half Bs[2][64*GLDA];
    __shared__ float Cs[64*68];
    int nb = blockIdx.x, mb = blockIdx.y;
    int n0 = nb*64, m0 = mb*128;
    int tid = threadIdx.x, warp = tid >> 5;
    int wm = warp >> 1, wn = warp & 1;
    const int K = Hdim;
    wmma::fragment<wmma::accumulator, 16,16,16, float> c[2][2];
    #pragma unroll
    for (int i = 0; i < 2; i++)
        #pragma unroll
        for (int j = 0; j < 2; j++)
            wmma::fill_fragment(c[i][j], 0.f);

    auto loadStage = [&](int stage, int kt) {
        int k0 = kt*32;
        #pragma unroll
        for (int rep = 0; rep < 2; rep++) {
            int ch = tid + rep*256;
            int row = ch >> 2, part = ch & 3;
            cp16(&As[stage][row*GLDA + part*8],
                 &d_OutAll[(size_t)(m0+row)*K + k0 + part*8]);
        }
        {
            int row = tid >> 2, part = tid & 3;
            cp16(&Bs[stage][row*GLDA + part*8],
                 &d_Wgen[(size_t)(n0+row)*K + k0 + part*8]);
        }
    };

    loadStage(0, 0);
    CP_COMMIT();
    const int nIter = K/32;
    for (int kt = 0; kt < nIter; ++kt) {
        int cur = kt & 1;
        if (kt + 1 < nIter) { loadStage(cur ^ 1, kt + 1); CP_COMMIT(); CP_WAIT(1); }
        else CP_WAIT(0);
        __syncthreads();
        #pragma unroll
        for (int s = 0; s < 32; s += 16) {
            wmma::fragment<wmma::matrix_a, 16,16,16, __half, wmma::row_major> a[2];
            wmma::fragment<wmma::matrix_b, 16,16,16, __half, wmma::col_major> bfr[2];
            #pragma unroll
            for (int i = 0; i < 2; i++)
                wmma::load_matrix_sync(a[i], &As[cur][(wm*32 + i*16)*GLDA + s], GLDA);
            #pragma unroll
            for (int j = 0; j < 2; j++)
                wmma::load_matrix_sync(bfr[j], &Bs[cur][(wn*32 + j*16)*GLDA + s], GLDA);
            #pragma unroll
            for (int i = 0; i < 2; i++)
                #pragma unroll
                for (int j = 0; j < 2; j++)
                    wmma::mma_sync(c[i][j], a[i], bfr[j], c[i][j]);
        }
        __syncthreads();
    }

    for (int hid = 0; hid < 2; ++hid) {
        if ((wm >> 1) == hid) {
            int wmL = wm & 1;
            #pragma unroll
            for (int i = 0; i < 2; i++)
                #pragma unroll
                for (int j = 0; j < 2; j++)
                    wmma::store_matrix_sync(&Cs[(wmL*32 + i*16)*68 + wn*32 + j*16],
                                            c[i][j], 68, wmma::mem_row_major);
        }
        __syncthreads();
        if (tid < 64) {
            int r = m0 + hid*64 + tid;
            float mx = -1e30f;
            for (int cc = 0; cc < 64; ++cc)
                mx = fmaxf(mx, Cs[tid*68 + cc] + bgen[n0 + cc]);
            float sm = 0.f;
            for (int cc = 0; cc < 64; ++cc)
                sm += expf(Cs[tid*68 + cc] + bgen[n0 + cc] - mx);
            d_partM[(size_t)r*NBLK + nb] = mx;
            d_partS[(size_t)r*NBLK + nb] = sm;
        }
        for (int e = tid; e < 64*64; e += 256) {
            int i = e >> 6, cc = e & 63;
            int r = m0 + hid*64 + i;
            logits[(size_t)r*Vdim + n0 + cc] = Cs[i*68 + cc] + bgen[n0 + cc];
        }
        __syncthreads();
    }
}

// ---------------------------------------------------------------------------
__global__ void k_combine() {
    int r = blockIdx.x, tid = threadIdx.x;
    float m = -1e30f, s = 0.f;
    for (int i = tid; i < NBLK; i += blockDim.x) {
        float mi = d_partM[(size_t)r*NBLK + i];
        float si = d_partS[(size_t)r*NBLK + i];
        float M = fmaxf(m, mi);
        s = s*expf(m - M) + si*expf(mi - M);
        m = M;
    }
    __shared__ float sm[128], ss[128];
    sm[tid] = m; ss[tid] = s;
    __syncthreads();
    for (int o = 64; o; o >>= 1) {
        if (tid < o) {
            float M = fmaxf(sm[tid], sm[tid+o]);
            ss[tid] = ss[tid]*expf(sm[tid] - M) + ss[tid+o]*expf(sm[tid+o] - M);
            sm[tid] = M;
        }
        __syncthreads();
    }
    if (!tid) d_lse[r] = sm[0] + logf(ss[0]);
}

__global__ void k_norm(float* __restrict__ logits) {
    int r = blockIdx.y;
    int i = blockIdx.x*blockDim.x + threadIdx.x;
    if (i < Vdim/4) {
        float4* p = (float4*)(logits + (size_t)r*Vdim);
        float l = d_lse[r];
        float4 v = p[i];
        v.x -= l; v.y -= l; v.z -= l; v.w -= l;
        p[i] = v;
    }
}

__global__ void k_final(float* __restrict__ tail) {
    int i = blockIdx.x*blockDim.x + threadIdx.x;
    const int BH = Bdim*Hdim;
    if (i < BH) {
        tail[i]        = d_h0f[i];
        tail[BH + i]   = d_h1f[i];
        tail[2*BH + i] = d_outf[i];
    }
}

// ---------------------------------------------------------------------------
extern "C" void kernel_launch(void* const* d_in, const int* in_sizes, int n_in,
                              void* d_out, int out_size) {
    (void)in_sizes; (void)n_in; (void)out_size;
    const int*   word_ids = (const int*)  d_in[0];
    const int*   spec_ids = (const int*)  d_in[1];
    const float* word_emb = (const float*)d_in[3];
    const float* spec_emb = (const float*)d_in[4];
    const float* wih0     = (const float*)d_in[5];
    const float* whh0     = (const float*)d_in[6];
    const float* bih0     = (const float*)d_in[7];
    const float* bhh0     = (const float*)d_in[8];
    const float* wih1     = (const float*)d_in[9];
    const float* whh1     = (const float*)d_in[10];
    const float* bih1     = (const float*)d_in[11];
    const float* bhh1     = (const float*)d_in[12];
    const float* Wa       = (const float*)d_in[13];
    const float* Wout     = (const float*)d_in[14];
    const float* Wgen     = (const float*)d_in[15];
    const float* bgen     = (const float*)d_in[16];
    const float* hidden   = (const float*)d_in[17];
    const float* pout     = (const float*)d_in[18];
    const float* context  = (const float*)d_in[19];
    float* outp = (float*)d_out;

    #define SYM(sym, ty, name) ty* name; { void* _p; cudaGetSymbolAddress(&_p, sym); name = (ty*)_p; }
    SYM(d_wih0H, __half, pwih0H)  SYM(d_wih0L, __half, pwih0L)
    SYM(d_whh0H, __half, pwhh0H)  SYM(d_whh0L, __half, pwhh0L)
    SYM(d_wih1H, __half, pwih1H)  SYM(d_wih1L, __half, pwih1L)
    SYM(d_whh1H, __half, pwhh1H)  SYM(d_whh1L, __half, pwhh1L)
    SYM(d_XfH,   __half, pXfH)    SYM(d_XfL,   __half, pXfL)
    SYM(d_h0H,   __half, ph0H)    SYM(d_h0L,   __half, ph0L)
    SYM(d_h1H,   __half, ph1H)    SYM(d_h1L,   __half, ph1L)
    SYM(d_h0f,   float,  ph0f)    SYM(d_h1f,   float,  ph1f)
    SYM(d_giP,   float,  pgiP)    SYM(d_ghP,   float,  pghP)
    SYM(d_preGi, float,  ppreGi)
    #undef SYM

    k_cvt_all<<<(CT + 255)/256, 256>>>((const float4*)wih0, (const float4*)whh0,
                                       (const float4*)wih1, (const float4*)whh1,
                                       (const float4*)Wa,   (const float4*)Wout,
                                       (const float4*)context, (const float4*)Wgen);
    k_embed_init<<<MROWS + 128, 256>>>(word_ids, spec_ids, word_emb, spec_emb, hidden, pout);
    k_prep<<<dim3(48, 32, 2), 128>>>();

    const int BH = Bdim*Hdim;
    for (int t = 0; t < Tdim; ++t) {
        k_gru_gemm<<<dim3(48,KSPL,2), 128>>>(
            pXfH + (size_t)t*BH, pXfL + (size_t)t*BH, Hdim, pwih0H + Edim, pwih0L + Edim, KX, pgiP,
            ph0H, ph0L, Hdim, pwhh0H, pwhh0L, Hdim, pghP, G3);
        k_gate<<<(BH + 255)/256, 256>>>(pgiP, pghP, ppreGi + (size_t)t*Bdim*G3,
                                        bih0, bhh0, ph0f, ph0H, ph0L, 0);
        k_gru_gemm<<<dim3(48,KSPL,2), 128>>>(
            ph0H, ph0L, Hdim, pwih1H, pwih1L, Hdim, pgiP,
            ph1H, ph1L, Hdim, pwhh1H, pwhh1L, Hdim, pghP, G3);
        k_gate<<<(BH + 255)/256, 256>>>(pgiP, pghP, (const float*)nullptr,
                                        bih1, bhh1, ph1f, ph1H, ph1L, 1);
        k_attn<<<Bdim, 256>>>(context);
        k_out<<<dim3(16,KSPL), 128>>>(t);
    }

    k_gen<<<dim3(NBLK, MROWS/128), 256>>>(bgen, outp);
    k_combine<<<MROWS, 128>>>();
    k_norm<<<dim3(32, MROWS), 256>>>(outp);
    k_final<<<(BH + 255)/256, 256>>>(outp + (size_t)MROWS*Vdim);
}